// round 1
// baseline (speedup 1.0000x reference)
#include <cuda_runtime.h>

#define BLOCK   256
#define ROWS_PT 4            // 4 rows per thread = 2 f32x2 pairs
#define B_TOTAL 131072
#define NFEAT   64
#define NNUM    48
#define NCAT    16
#define NCLS    32
#define H0      40
#define H1      20

typedef unsigned long long u64;

__device__ __forceinline__ u64 fma2(u64 a, u64 b, u64 c) {
    u64 d;
    asm("fma.rn.f32x2 %0, %1, %2, %3;" : "=l"(d) : "l"(a), "l"(b), "l"(c));
    return d;
}
__device__ __forceinline__ u64 pack2(float lo, float hi) {
    u64 d;
    asm("mov.b64 %0, {%1, %2};" : "=l"(d) : "f"(lo), "f"(hi));
    return d;
}
__device__ __forceinline__ void unpack2(u64 v, float& lo, float& hi) {
    asm("mov.b64 {%0, %1}, %2;" : "=f"(lo), "=f"(hi) : "l"(v));
}
__device__ __forceinline__ u64 relu2(u64 v) {
    float lo, hi;
    unpack2(v, lo, hi);
    lo = fmaxf(lo, 0.0f);
    hi = fmaxf(hi, 0.0f);
    return pack2(lo, hi);
}

// One block = (feature f, chunk of 1024 rows). Weights pre-splatted into
// shared as f32x2 pairs so the mainloop is LDS.64 (broadcast) + FFMA2 only.
__global__ __launch_bounds__(BLOCK)
void gam_num_kernel(const float* __restrict__ inputs,
                    const float* __restrict__ W0, const float* __restrict__ b0,
                    const float* __restrict__ W1, const float* __restrict__ b1,
                    const float* __restrict__ W2, const float* __restrict__ b2,
                    float* __restrict__ out)
{
    __shared__ u64 sW0[H0], sB0[H0], sW1[H0 * H1], sB1[H1], sW2[H1];
    __shared__ u64 sB2;

    const int f   = blockIdx.y;
    const int tid = threadIdx.x;

    // ---- load + splat this feature's weights into shared ----
    for (int i = tid; i < H0; i += BLOCK) {
        float w = W0[f * H0 + i];  sW0[i] = pack2(w, w);
        float c = b0[f * H0 + i];  sB0[i] = pack2(c, c);
    }
    for (int i = tid; i < H0 * H1; i += BLOCK) {
        float w = W1[f * H0 * H1 + i];  sW1[i] = pack2(w, w);
    }
    for (int i = tid; i < H1; i += BLOCK) {
        float c = b1[f * H1 + i];  sB1[i] = pack2(c, c);
        float w = W2[f * H1 + i];  sW2[i] = pack2(w, w);
    }
    if (tid == 0) { float c = b2[f]; sB2 = pack2(c, c); }
    __syncthreads();

    const int row0 = (blockIdx.x * BLOCK + tid) * ROWS_PT;
    if (row0 >= B_TOTAL) return;

    // column-f reads: strided 256B, but input (33.5MB) is L2-resident
    const float x0 = inputs[(row0 + 0) * NFEAT + f];
    const float x1 = inputs[(row0 + 1) * NFEAT + f];
    const float x2 = inputs[(row0 + 2) * NFEAT + f];
    const float x3 = inputs[(row0 + 3) * NFEAT + f];
    const u64 xa = pack2(x0, x1);
    const u64 xb = pack2(x2, x3);

    // h1 accumulators, init with b1
    u64 h1a[H1], h1b[H1];
    #pragma unroll
    for (int p = 0; p < H1; p++) { h1a[p] = sB1[p]; h1b[p] = sB1[p]; }

    // fused layer0+layer1: h0[o] computed on the fly, feeds 2x20 FFMA2s
    #pragma unroll 4
    for (int o = 0; o < H0; o++) {
        const u64 w0 = sW0[o];
        const u64 c0 = sB0[o];
        const u64 ha = relu2(fma2(xa, w0, c0));
        const u64 hb = relu2(fma2(xb, w0, c0));
        #pragma unroll
        for (int p = 0; p < H1; p++) {
            const u64 w = sW1[o * H1 + p];   // LDS.64 broadcast, feeds 2 FFMA2
            h1a[p] = fma2(ha, w, h1a[p]);
            h1b[p] = fma2(hb, w, h1b[p]);
        }
    }

    // layer2: relu(h1) dot W2 + b2
    u64 oa = sB2, ob = sB2;
    #pragma unroll
    for (int p = 0; p < H1; p++) {
        const u64 w = sW2[p];
        oa = fma2(relu2(h1a[p]), w, oa);
        ob = fma2(relu2(h1b[p]), w, ob);
    }

    float o0, o1, o2, o3;
    unpack2(oa, o0, o1);
    unpack2(ob, o2, o3);
    out[(row0 + 0) * NFEAT + f] = o0;
    out[(row0 + 1) * NFEAT + f] = o1;
    out[(row0 + 2) * NFEAT + f] = o2;
    out[(row0 + 3) * NFEAT + f] = o3;
}

// Categorical path: out[:, 48+c] = class_bias[c, (int)inputs[:, 48+c]]
__global__ __launch_bounds__(256)
void gam_cat_kernel(const float* __restrict__ inputs,
                    const float* __restrict__ class_bias,
                    float* __restrict__ out)
{
    const int i = blockIdx.x * blockDim.x + threadIdx.x;  // over B*16
    if (i >= B_TOTAL * NCAT) return;
    const int row = i >> 4;
    const int c   = i & 15;
    const int idx = (int)inputs[row * NFEAT + NNUM + c];
    out[row * NFEAT + NNUM + c] = class_bias[c * NCLS + idx];
}

extern "C" void kernel_launch(void* const* d_in, const int* in_sizes, int n_in,
                              void* d_out, int out_size)
{
    const float* inputs     = (const float*)d_in[0];
    const float* W0         = (const float*)d_in[1];
    const float* b0         = (const float*)d_in[2];
    const float* W1         = (const float*)d_in[3];
    const float* b1         = (const float*)d_in[4];
    const float* W2         = (const float*)d_in[5];
    const float* b2         = (const float*)d_in[6];
    const float* class_bias = (const float*)d_in[7];
    float* out = (float*)d_out;

    dim3 grid(B_TOTAL / (BLOCK * ROWS_PT), NNUM);   // 128 x 48
    gam_num_kernel<<<grid, BLOCK>>>(inputs, W0, b0, W1, b1, W2, b2, out);

    const int cat_total = B_TOTAL * NCAT;
    gam_cat_kernel<<<(cat_total + 255) / 256, 256>>>(inputs, class_bias, out);
}